// round 13
// baseline (speedup 1.0000x reference)
#include <cuda_runtime.h>
#include <mma.h>
#include <cstdint>
#include <cfloat>

using namespace nvcuda;

#define NDOMS   262144
#define NPULSES 4194304
#define EMBED   64

// ---- static scratch (no allocs allowed) ----
__device__ int   g_count [NDOMS];
__device__ int   g_offset[NDOMS];
__device__ int   g_rank  [NPULSES];
__device__ int   g_perm  [NPULSES];
__device__ int   g_is64;
__device__ unsigned long long g_scanpk[256];   // (state<<32)|value, 1=agg,2=incl
__device__ float g_concat[(size_t)NDOMS * 128];

__device__ __forceinline__ int load_idx(const void* __restrict__ idx, int i) {
    if (g_is64) return (int)((const long long*)idx)[i];
    return ((const int*)idx)[i];
}

// ---------------------------------------------------------------- init (merged)
__global__ void k_init(const unsigned int* __restrict__ idx32) {
    int b = blockIdx.x, t = threadIdx.x;
    if (b < 64) {
        ((int4*)g_count)[b * 1024 + t] = make_int4(0, 0, 0, 0);
    } else {
        if (t < 32) {
            unsigned int v = idx32[2 * (t * 4 + 0) + 1]
                           | idx32[2 * (t * 4 + 1) + 1]
                           | idx32[2 * (t * 4 + 2) + 1]
                           | idx32[2 * (t * 4 + 3) + 1];
            unsigned int any = __ballot_sync(0xffffffffu, v != 0u);
            if (t == 0) g_is64 = (any == 0u) ? 1 : 0;
        } else if (t >= 32 && t < 288) {
            g_scanpk[t - 32] = 0ULL;
        }
    }
}

// ---------------------------------------------------------------- histogram + rank (ILP 8)
__global__ void __launch_bounds__(256) k_hist(const void* __restrict__ idx) {
    int base = blockIdx.x * 2048 + threadIdx.x;
    int d[8];
    #pragma unroll
    for (int u = 0; u < 8; u++)
        d[u] = load_idx(idx, base + u * 256);
    int pos[8];
    #pragma unroll
    for (int u = 0; u < 8; u++)
        pos[u] = atomicAdd(&g_count[d[u]], 1);
    #pragma unroll
    for (int u = 0; u < 8; u++)
        g_rank[base + u * 256] = pos[u];
}

// ---------------------------------------------------------------- single-pass scan
__global__ void k_scan() {
    __shared__ int sh[1024];
    __shared__ int s_prefix;
    int t = threadIdx.x, b = blockIdx.x;
    int i = b * 1024 + t;
    int v = g_count[i];
    sh[t] = v;
    __syncthreads();
    for (int off = 1; off < 1024; off <<= 1) {
        int add = (t >= off) ? sh[t - off] : 0;
        __syncthreads();
        sh[t] += add;
        __syncthreads();
    }
    if (t == 0) {
        int agg = sh[1023];
        int prefix = 0;
        if (b == 0) {
            atomicExch(&g_scanpk[0], (2ULL << 32) | (unsigned int)agg);
        } else {
            atomicExch(&g_scanpk[b], (1ULL << 32) | (unsigned int)agg);
            int j = b - 1;
            while (true) {
                unsigned long long pk = atomicAdd(&g_scanpk[j], 0ULL);
                unsigned int st = (unsigned int)(pk >> 32);
                if (st == 0u) continue;
                prefix += (int)(unsigned int)pk;
                if (st == 2u) break;
                j--;
            }
            atomicExch(&g_scanpk[b], (2ULL << 32) | (unsigned int)(prefix + agg));
        }
        s_prefix = prefix;
    }
    __syncthreads();
    g_offset[i] = s_prefix + sh[t] - v;
}

// ---------------------------------------------------------------- scatter (atomic-free, ILP 8)
__global__ void __launch_bounds__(256) k_scatter(const void* __restrict__ idx) {
    int base = blockIdx.x * 2048 + threadIdx.x;
    int d[8], r[8];
    #pragma unroll
    for (int u = 0; u < 8; u++)
        d[u] = load_idx(idx, base + u * 256);
    #pragma unroll
    for (int u = 0; u < 8; u++)
        r[u] = g_rank[base + u * 256];
    int off[8];
    #pragma unroll
    for (int u = 0; u < 8; u++)
        off[u] = g_offset[d[u]];
    #pragma unroll
    for (int u = 0; u < 8; u++)
        g_perm[off[u] + r[u]] = base + u * 256;
}

// ---------------------------------------------------------------- pool (R9 proven)
__global__ void __launch_bounds__(256) k_pool(const float* __restrict__ emb) {
    int gw   = (blockIdx.x * blockDim.x + threadIdx.x) >> 5;
    int lane = threadIdx.x & 31;
    if (gw >= NDOMS) return;

    int start = g_offset[gw];
    int cnt   = g_count[gw];

    const float2* e2 = (const float2*)emb;
    float sx = 0.f, sy = 0.f;
    float mx = -FLT_MAX, my = -FLT_MAX;

    for (int i = 0; i < cnt; i += 8) {
        int m = cnt - i;
        int p[8];
        #pragma unroll
        for (int u = 0; u < 8; u++) {
            int uu = (u < m) ? u : (m - 1);
            p[u] = g_perm[start + i + uu];
        }
        float2 v[8];
        #pragma unroll
        for (int u = 0; u < 8; u++)
            v[u] = __ldcs(&e2[(size_t)p[u] * 32 + lane]);
        #pragma unroll
        for (int u = 0; u < 8; u++) {
            if (u < m) {
                sx += v[u].x; sy += v[u].y;
                mx = fmaxf(mx, v[u].x); my = fmaxf(my, v[u].y);
            }
        }
    }

    float inv = 1.0f / (float)(cnt > 0 ? cnt : 1);
    if (cnt == 0) { mx = 0.f; my = 0.f; }

    float2* crow = (float2*)(g_concat + (size_t)gw * 128);
    crow[lane]      = make_float2(sx * inv, sy * inv);
    crow[32 + lane] = make_float2(mx, my);
}

// ---------------------------------------------------------------- GEMM: 3xTF32 wmma
// C[262144,64] = A[262144,128] @ W^T + bias.  B loads W directly (col_major:
// W[j*128+k] == (k,j) col-major, ldm=128).  3xTF32: x=hi+lo; lo*hi+hi*lo+hi*hi.
// smem: As 32x128 (16KB) + Ws 64x128 (32KB) = 48KB. 128 thr = 4 warps;
// warp w -> n-tile w (cols 16w..16w+15), 2 m-tiles.
#define GEMM_BLOCKS 592
#define NTILES (NDOMS / 32)

__global__ void __launch_bounds__(128) k_gemm(const float* __restrict__ Wg,
                                              const float* __restrict__ bias,
                                              float* __restrict__ out) {
    extern __shared__ float sm[];
    float* As = sm;                 // [32][128]; reused as C [32][64] in epilogue
    float* Ws = sm + 32 * 128;      // [64][128] original W layout

    int tid = threadIdx.x, wid = tid >> 5;

    // stage W once per block
    const float4* W4 = (const float4*)Wg;
    float4* Ws4 = (float4*)Ws;
    #pragma unroll
    for (int i = 0; i < 16; i++)
        Ws4[tid + i * 128] = W4[tid + i * 128];

    float4* As4 = (float4*)As;

    float4 pre[8];
    int tile = blockIdx.x;
    {
        const float4* A4 = (const float4*)(g_concat + (size_t)tile * 32 * 128);
        #pragma unroll
        for (int i = 0; i < 8; i++) pre[i] = A4[tid + i * 128];
    }

    for (; tile < NTILES; tile += GEMM_BLOCKS) {
        __syncthreads();                        // prev C readers done
        #pragma unroll
        for (int i = 0; i < 8; i++) As4[tid + i * 128] = pre[i];
        __syncthreads();

        int nxt = tile + GEMM_BLOCKS;
        if (nxt < NTILES) {
            const float4* A4 = (const float4*)(g_concat + (size_t)nxt * 32 * 128);
            #pragma unroll
            for (int i = 0; i < 8; i++) pre[i] = A4[tid + i * 128];
        }

        wmma::fragment<wmma::accumulator, 16, 16, 8, float> acc0, acc1;
        wmma::fill_fragment(acc0, 0.0f);
        wmma::fill_fragment(acc1, 0.0f);

        #pragma unroll 4
        for (int ks = 0; ks < 16; ks++) {
            wmma::fragment<wmma::matrix_b, 16, 16, 8, wmma::precision::tf32,
                           wmma::col_major> b_hi, b_lo;
            wmma::load_matrix_sync(b_hi, Ws + wid * 16 * 128 + ks * 8, 128);
            #pragma unroll
            for (int t = 0; t < b_hi.num_elements; t++) {
                float x = b_hi.x[t];
                float h = wmma::__float_to_tf32(x);
                b_hi.x[t] = h;
                b_lo.x[t] = wmma::__float_to_tf32(x - h);
            }
            wmma::fragment<wmma::matrix_a, 16, 16, 8, wmma::precision::tf32,
                           wmma::row_major> a_hi0, a_lo0, a_hi1, a_lo1;
            wmma::load_matrix_sync(a_hi0, As + ks * 8, 128);
            wmma::load_matrix_sync(a_hi1, As + 16 * 128 + ks * 8, 128);
            #pragma unroll
            for (int t = 0; t < a_hi0.num_elements; t++) {
                float x = a_hi0.x[t];
                float h = wmma::__float_to_tf32(x);
                a_hi0.x[t] = h;
                a_lo0.x[t] = wmma::__float_to_tf32(x - h);
                x = a_hi1.x[t];
                h = wmma::__float_to_tf32(x);
                a_hi1.x[t] = h;
                a_lo1.x[t] = wmma::__float_to_tf32(x - h);
            }
            wmma::mma_sync(acc0, a_lo0, b_hi, acc0);
            wmma::mma_sync(acc0, a_hi0, b_lo, acc0);
            wmma::mma_sync(acc0, a_hi0, b_hi, acc0);
            wmma::mma_sync(acc1, a_lo1, b_hi, acc1);
            wmma::mma_sync(acc1, a_hi1, b_lo, acc1);
            wmma::mma_sync(acc1, a_hi1, b_hi, acc1);
        }

        __syncthreads();                        // all warps done reading As
        wmma::store_matrix_sync(As + wid * 16, acc0, 64, wmma::mem_row_major);
        wmma::store_matrix_sync(As + 16 * 64 + wid * 16, acc1, 64, wmma::mem_row_major);
        __syncthreads();

        // write out with bias: 32 rows x 16 float4 = 512 chunks, 4 per thread
        int dom0 = tile * 32;
        #pragma unroll
        for (int i = 0; i < 4; i++) {
            int s   = tid + i * 128;
            int row = s >> 4, c4 = s & 15;
            float4 v  = ((const float4*)As)[row * 16 + c4];
            float4 bb = ((const float4*)bias)[c4];
            v.x += bb.x; v.y += bb.y; v.z += bb.z; v.w += bb.w;
            *(float4*)&out[(size_t)(dom0 + row) * 64 + c4 * 4] = v;
        }
    }
}

// ---------------------------------------------------------------- launch
extern "C" void kernel_launch(void* const* d_in, const int* in_sizes, int n_in,
                              void* d_out, int out_size) {
    const float* emb = nullptr;
    const void*  idx = nullptr;
    const float* W   = nullptr;
    const float* b   = nullptr;
    for (int i = 0; i < n_in; i++) {
        long long sz = in_sizes[i];
        if (sz == 268435456LL || sz == 1073741824LL)           emb = (const float*)d_in[i];
        else if (sz == 4194304LL || sz == 33554432LL
                                 || sz == 16777216LL)          idx = d_in[i];
        else if (sz == 8192LL || sz == 32768LL)                W   = (const float*)d_in[i];
        else if (sz == 64LL  || sz == 256LL)                   b   = (const float*)d_in[i];
    }
    if (!emb || !idx || !W || !b) {
        emb = (const float*)d_in[0];
        idx = d_in[1];
        if (n_in >= 5) { W = (const float*)d_in[3]; b = (const float*)d_in[4]; }
        else           { W = (const float*)d_in[2]; b = (const float*)d_in[3]; }
    }
    float* out = (float*)d_out;

    k_init   <<<65, 1024>>>((const unsigned int*)idx);
    k_hist   <<<NPULSES / 2048, 256>>>(idx);
    k_scan   <<<256, 1024>>>();
    k_scatter<<<NPULSES / 2048, 256>>>(idx);
    k_pool   <<<NDOMS / 8, 256>>>(emb);
    k_gemm   <<<GEMM_BLOCKS, 128, 49152>>>(W, b, out);
}

// round 14
// speedup vs baseline: 1.2810x; 1.2810x over previous
#include <cuda_runtime.h>
#include <cstdint>
#include <cfloat>

#define NDOMS   262144
#define NPULSES 4194304
#define EMBED   64

// ---- static scratch (no allocs allowed) ----
__device__ int   g_count [NDOMS];
__device__ int   g_offset[NDOMS];
__device__ int   g_rank  [NPULSES];
__device__ int   g_perm  [NPULSES];
__device__ int   g_is64;
__device__ unsigned long long g_scanpk[256];   // (state<<32)|value, 1=agg,2=incl
__device__ float g_wt[128 * 64];               // W transposed: g_wt[k*64+j]=W[j][k]
__device__ float g_concat[(size_t)NDOMS * 128];

__device__ __forceinline__ int load_idx(const void* __restrict__ idx, int i) {
    if (g_is64) return (int)((const long long*)idx)[i];
    return ((const int*)idx)[i];
}

// ---------------------------------------------------------------- init (merged)
__global__ void k_init(const unsigned int* __restrict__ idx32,
                       const float* __restrict__ W) {
    int b = blockIdx.x, t = threadIdx.x;
    if (b < 64) {
        ((int4*)g_count)[b * 1024 + t] = make_int4(0, 0, 0, 0);
    } else if (b == 64) {
        if (t < 32) {
            unsigned int v = idx32[2 * (t * 4 + 0) + 1]
                           | idx32[2 * (t * 4 + 1) + 1]
                           | idx32[2 * (t * 4 + 2) + 1]
                           | idx32[2 * (t * 4 + 3) + 1];
            unsigned int any = __ballot_sync(0xffffffffu, v != 0u);
            if (t == 0) g_is64 = (any == 0u) ? 1 : 0;
        } else if (t >= 32 && t < 288) {
            g_scanpk[t - 32] = 0ULL;
        }
    } else {
        int s = (b - 65) * 1024 + t;          // 8192 elems
        int j = s >> 7, k = s & 127;
        g_wt[k * 64 + j] = W[s];
    }
}

// ---------------------------------------------------------------- histogram + rank (ILP 8)
// atomicAdd return = rank of pulse within its dom (coalesced store to g_rank).
__global__ void __launch_bounds__(256) k_hist(const void* __restrict__ idx) {
    int base = blockIdx.x * 2048 + threadIdx.x;
    int d[8];
    #pragma unroll
    for (int u = 0; u < 8; u++)
        d[u] = load_idx(idx, base + u * 256);
    int pos[8];
    #pragma unroll
    for (int u = 0; u < 8; u++)
        pos[u] = atomicAdd(&g_count[d[u]], 1);
    #pragma unroll
    for (int u = 0; u < 8; u++)
        g_rank[base + u * 256] = pos[u];
}

// ---------------------------------------------------------------- single-pass scan
__global__ void k_scan() {
    __shared__ int sh[1024];
    __shared__ int s_prefix;
    int t = threadIdx.x, b = blockIdx.x;
    int i = b * 1024 + t;
    int v = g_count[i];
    sh[t] = v;
    __syncthreads();
    for (int off = 1; off < 1024; off <<= 1) {
        int add = (t >= off) ? sh[t - off] : 0;
        __syncthreads();
        sh[t] += add;
        __syncthreads();
    }
    if (t == 0) {
        int agg = sh[1023];
        int prefix = 0;
        if (b == 0) {
            atomicExch(&g_scanpk[0], (2ULL << 32) | (unsigned int)agg);
        } else {
            atomicExch(&g_scanpk[b], (1ULL << 32) | (unsigned int)agg);
            int j = b - 1;
            while (true) {
                unsigned long long pk = atomicAdd(&g_scanpk[j], 0ULL);
                unsigned int st = (unsigned int)(pk >> 32);
                if (st == 0u) continue;
                prefix += (int)(unsigned int)pk;
                if (st == 2u) break;
                j--;
            }
            atomicExch(&g_scanpk[b], (2ULL << 32) | (unsigned int)(prefix + agg));
        }
        s_prefix = prefix;
    }
    __syncthreads();
    g_offset[i] = s_prefix + sh[t] - v;
}

// ---------------------------------------------------------------- scatter (atomic-free, ILP 8)
__global__ void __launch_bounds__(256) k_scatter(const void* __restrict__ idx) {
    int base = blockIdx.x * 2048 + threadIdx.x;
    int d[8], r[8];
    #pragma unroll
    for (int u = 0; u < 8; u++)
        d[u] = load_idx(idx, base + u * 256);
    #pragma unroll
    for (int u = 0; u < 8; u++)
        r[u] = g_rank[base + u * 256];
    int off[8];
    #pragma unroll
    for (int u = 0; u < 8; u++)
        off[u] = g_offset[d[u]];
    #pragma unroll
    for (int u = 0; u < 8; u++)
        g_perm[off[u] + r[u]] = base + u * 256;
}

// ---------------------------------------------------------------- pool (R10 proven)
__global__ void __launch_bounds__(256) k_pool(const float* __restrict__ emb) {
    int gw   = (blockIdx.x * blockDim.x + threadIdx.x) >> 5;
    int lane = threadIdx.x & 31;
    if (gw >= NDOMS) return;

    int start = g_offset[gw];
    int cnt   = g_count[gw];

    const float2* e2 = (const float2*)emb;
    float sx = 0.f, sy = 0.f;
    float mx = -FLT_MAX, my = -FLT_MAX;

    for (int i = 0; i < cnt; i += 8) {
        int m = cnt - i;
        int p[8];
        #pragma unroll
        for (int u = 0; u < 8; u++) {
            int uu = (u < m) ? u : (m - 1);
            p[u] = g_perm[start + i + uu];
        }
        float2 v[8];
        #pragma unroll
        for (int u = 0; u < 8; u++)
            v[u] = __ldcs(&e2[(size_t)p[u] * 32 + lane]);
        #pragma unroll
        for (int u = 0; u < 8; u++) {
            if (u < m) {
                sx += v[u].x; sy += v[u].y;
                mx = fmaxf(mx, v[u].x); my = fmaxf(my, v[u].y);
            }
        }
    }

    float inv = 1.0f / (float)(cnt > 0 ? cnt : 1);
    if (cnt == 0) { mx = 0.f; my = 0.f; }

    float2* crow = (float2*)(g_concat + (size_t)gw * 128);
    __stcs(&crow[lane],      make_float2(sx * inv, sy * inv));
    __stcs(&crow[32 + lane], make_float2(mx, my));
}

// ---------------------------------------------------------------- projection GEMM (R10 proven)
#define GEMM_BLOCKS 592
#define NTILES (NDOMS / 32)

__global__ void __launch_bounds__(128) k_gemm(const float* __restrict__ bias,
                                              float* __restrict__ out) {
    extern __shared__ float sm[];
    float* As = sm;                 // [32][128]
    float* Bs = sm + 32 * 128;      // [128][64]

    int tid = threadIdx.x;

    const float4* Wt4 = (const float4*)g_wt;
    float4* Bs4 = (float4*)Bs;
    #pragma unroll
    for (int i = 0; i < 16; i++)
        Bs4[tid + i * 128] = Wt4[tid + i * 128];

    int tj = tid & 15, tm = tid >> 4;
    int m0 = tm * 4, j0 = tj * 4;
    float4 bv = *(const float4*)&bias[j0];

    float4* As4 = (float4*)As;

    float4 pre[8];
    int tile = blockIdx.x;
    if (tile < NTILES) {
        const float4* A4 = (const float4*)(g_concat + (size_t)tile * 32 * 128);
        #pragma unroll
        for (int i = 0; i < 8; i++) pre[i] = __ldcs(&A4[tid + i * 128]);
    }

    for (; tile < NTILES; tile += GEMM_BLOCKS) {
        __syncthreads();
        #pragma unroll
        for (int i = 0; i < 8; i++) As4[tid + i * 128] = pre[i];
        __syncthreads();

        int nxt = tile + GEMM_BLOCKS;
        if (nxt < NTILES) {
            const float4* A4 = (const float4*)(g_concat + (size_t)nxt * 32 * 128);
            #pragma unroll
            for (int i = 0; i < 8; i++) pre[i] = __ldcs(&A4[tid + i * 128]);
        }

        float c[4][4];
        #pragma unroll
        for (int i = 0; i < 4; i++)
            #pragma unroll
            for (int j = 0; j < 4; j++) c[i][j] = 0.f;

        #pragma unroll 8
        for (int k = 0; k < 128; k += 2) {
            float2 a0 = *(const float2*)&As[(m0 + 0) * 128 + k];
            float2 a1 = *(const float2*)&As[(m0 + 1) * 128 + k];
            float2 a2 = *(const float2*)&As[(m0 + 2) * 128 + k];
            float2 a3 = *(const float2*)&As[(m0 + 3) * 128 + k];
            float4 b0 = *(const float4*)&Bs[k * 64 + j0];
            float4 b1 = *(const float4*)&Bs[(k + 1) * 64 + j0];
            c[0][0] = fmaf(a0.x, b0.x, c[0][0]); c[0][1] = fmaf(a0.x, b0.y, c[0][1]);
            c[0][2] = fmaf(a0.x, b0.z, c[0][2]); c[0][3] = fmaf(a0.x, b0.w, c[0][3]);
            c[1][0] = fmaf(a1.x, b0.x, c[1][0]); c[1][1] = fmaf(a1.x, b0.y, c[1][1]);
            c[1][2] = fmaf(a1.x, b0.z, c[1][2]); c[1][3] = fmaf(a1.x, b0.w, c[1][3]);
            c[2][0] = fmaf(a2.x, b0.x, c[2][0]); c[2][1] = fmaf(a2.x, b0.y, c[2][1]);
            c[2][2] = fmaf(a2.x, b0.z, c[2][2]); c[2][3] = fmaf(a2.x, b0.w, c[2][3]);
            c[3][0] = fmaf(a3.x, b0.x, c[3][0]); c[3][1] = fmaf(a3.x, b0.y, c[3][1]);
            c[3][2] = fmaf(a3.x, b0.z, c[3][2]); c[3][3] = fmaf(a3.x, b0.w, c[3][3]);
            c[0][0] = fmaf(a0.y, b1.x, c[0][0]); c[0][1] = fmaf(a0.y, b1.y, c[0][1]);
            c[0][2] = fmaf(a0.y, b1.z, c[0][2]); c[0][3] = fmaf(a0.y, b1.w, c[0][3]);
            c[1][0] = fmaf(a1.y, b1.x, c[1][0]); c[1][1] = fmaf(a1.y, b1.y, c[1][1]);
            c[1][2] = fmaf(a1.y, b1.z, c[1][2]); c[1][3] = fmaf(a1.y, b1.w, c[1][3]);
            c[2][0] = fmaf(a2.y, b1.x, c[2][0]); c[2][1] = fmaf(a2.y, b1.y, c[2][1]);
            c[2][2] = fmaf(a2.y, b1.z, c[2][2]); c[2][3] = fmaf(a2.y, b1.w, c[2][3]);
            c[3][0] = fmaf(a3.y, b1.x, c[3][0]); c[3][1] = fmaf(a3.y, b1.y, c[3][1]);
            c[3][2] = fmaf(a3.y, b1.z, c[3][2]); c[3][3] = fmaf(a3.y, b1.w, c[3][3]);
        }

        int dom0 = tile * 32;
        #pragma unroll
        for (int i = 0; i < 4; i++) {
            float4 r;
            r.x = c[i][0] + bv.x; r.y = c[i][1] + bv.y;
            r.z = c[i][2] + bv.z; r.w = c[i][3] + bv.w;
            __stcs((float4*)&out[(size_t)(dom0 + m0 + i) * 64 + j0], r);
        }
    }
}

// ---------------------------------------------------------------- launch
extern "C" void kernel_launch(void* const* d_in, const int* in_sizes, int n_in,
                              void* d_out, int out_size) {
    const float* emb = nullptr;
    const void*  idx = nullptr;
    const float* W   = nullptr;
    const float* b   = nullptr;
    for (int i = 0; i < n_in; i++) {
        long long sz = in_sizes[i];
        if (sz == 268435456LL || sz == 1073741824LL)           emb = (const float*)d_in[i];
        else if (sz == 4194304LL || sz == 33554432LL
                                 || sz == 16777216LL)          idx = d_in[i];
        else if (sz == 8192LL || sz == 32768LL)                W   = (const float*)d_in[i];
        else if (sz == 64LL  || sz == 256LL)                   b   = (const float*)d_in[i];
    }
    if (!emb || !idx || !W || !b) {
        emb = (const float*)d_in[0];
        idx = d_in[1];
        if (n_in >= 5) { W = (const float*)d_in[3]; b = (const float*)d_in[4]; }
        else           { W = (const float*)d_in[2]; b = (const float*)d_in[3]; }
    }
    float* out = (float*)d_out;

    k_init   <<<73, 1024>>>((const unsigned int*)idx, W);
    k_hist   <<<NPULSES / 2048, 256>>>(idx);
    k_scan   <<<256, 1024>>>();
    k_scatter<<<NPULSES / 2048, 256>>>(idx);
    k_pool   <<<NDOMS / 8, 256>>>(emb);
    k_gemm   <<<GEMM_BLOCKS, 128, 49152>>>(b, out);
}